// round 1
// baseline (speedup 1.0000x reference)
#include <cuda_runtime.h>
#include <cstdint>

#define B_SZ  256
#define A_DIM 128
#define HID   512
#define TM    32          // (i,j) pairs per block
#define KT    16          // k-tile depth
#define NT    (HID / KT)  // 32 k-tiles

// Scratch for the x / y projections (device globals: no allocation allowed)
__device__ float g_hx[B_SZ * HID];  // hx = x @ Wx + b0
__device__ float g_hy[B_SZ * HID];  // hy = y @ Wy

// ---------------- packed fp32x2 helpers (sm_100+) ----------------
__device__ __forceinline__ unsigned long long pack2(float lo, float hi) {
    unsigned long long r;
    asm("mov.b64 %0, {%1, %2};" : "=l"(r) : "f"(lo), "f"(hi));
    return r;
}
__device__ __forceinline__ void unpack2(unsigned long long v, float& lo, float& hi) {
    asm("mov.b64 {%0, %1}, %2;" : "=f"(lo), "=f"(hi) : "l"(v));
}
__device__ __forceinline__ unsigned long long ffma2(unsigned long long a,
                                                    unsigned long long b,
                                                    unsigned long long c) {
    unsigned long long d;
    asm("fma.rn.f32x2 %0, %1, %2, %3;" : "=l"(d) : "l"(a), "l"(b), "l"(c));
    return d;
}
__device__ __forceinline__ void cp16(uint32_t dst_smem, const void* src) {
    asm volatile("cp.async.cg.shared.global [%0], [%1], 16;" :: "r"(dst_smem), "l"(src));
}

// ---------------- kernel 1: hx = x@Wx + b0, hy = y@Wy ----------------
__global__ void __launch_bounds__(128, 8) proj_kernel(
    const float* __restrict__ x, const float* __restrict__ y,
    const float* __restrict__ Wx, const float* __restrict__ Wy,
    const float* __restrict__ b0)
{
    __shared__ float sx[A_DIM];
    const int b = blockIdx.x, tid = threadIdx.x;

    const float* src; const float* W; float* dst; bool addb;
    if (b < B_SZ) { src = x + b * A_DIM;          W = Wx; dst = g_hx + b * HID;          addb = true;  }
    else          { src = y + (b - B_SZ) * A_DIM; W = Wy; dst = g_hy + (b - B_SZ) * HID; addb = false; }

    sx[tid] = src[tid];
    __syncthreads();

    const float4* W4 = (const float4*)W;   // [A_DIM][HID/4]
    float4 acc = make_float4(0.f, 0.f, 0.f, 0.f);
#pragma unroll 8
    for (int k = 0; k < A_DIM; ++k) {
        float xv = sx[k];
        float4 w = W4[k * (HID / 4) + tid];
        acc.x = fmaf(xv, w.x, acc.x);
        acc.y = fmaf(xv, w.y, acc.y);
        acc.z = fmaf(xv, w.z, acc.z);
        acc.w = fmaf(xv, w.w, acc.w);
    }
    if (addb) {
        float4 bb = ((const float4*)b0)[tid];
        acc.x += bb.x; acc.y += bb.y; acc.z += bb.z; acc.w += bb.w;
    }
    ((float4*)dst)[tid] = acc;
}

// ---------------- fused MLP building blocks ----------------
__device__ __forceinline__ void issue_wtile(const float4* __restrict__ Wg,
                                            float* wbuf, int t, int tid)
{
    uint32_t base = (uint32_t)__cvta_generic_to_shared(wbuf + (t & 1) * KT * HID);
#pragma unroll
    for (int e = 0; e < (KT * HID / 4) / 256; ++e) {   // 8 float4 per thread
        int f = tid + e * 256;                          // f = k*128 + c4
        cp16(base + f * 16, Wg + t * KT * (HID / 4) + f);
    }
    asm volatile("cp.async.commit_group;");
}

// GEMM layer: sh_out = relu(sh_in @ W + bias), sh_in/sh_out are [TM][HID] fp32 in SMEM.
__device__ __forceinline__ void mlp_layer(const float* __restrict__ W,
                                          const float* __restrict__ bias,
                                          const float* sh_in, float* sh_out,
                                          float* wbuf, int tid)
{
    const int tx = tid & 31;   // column group: cols tx*4 + g*128, g=0..3
    const int ty = tid >> 5;   // row group: rows ty*4 + rr
    const float4* Wg = (const float4*)W;

    float4 bq[4];
    const float4* b4 = (const float4*)bias;
#pragma unroll
    for (int g = 0; g < 4; ++g) bq[g] = b4[tx + g * 32];

    unsigned long long acc[4][4][2];
#pragma unroll
    for (int rr = 0; rr < 4; ++rr)
#pragma unroll
        for (int g = 0; g < 4; ++g) { acc[rr][g][0] = 0ull; acc[rr][g][1] = 0ull; }

    issue_wtile(Wg, wbuf, 0, tid);

    for (int t = 0; t < NT; ++t) {
        if (t + 1 < NT) {
            issue_wtile(Wg, wbuf, t + 1, tid);
            asm volatile("cp.async.wait_group 1;");
        } else {
            asm volatile("cp.async.wait_group 0;");
        }
        __syncthreads();

        const ulonglong2* wb = (const ulonglong2*)(wbuf + (t & 1) * KT * HID);
#pragma unroll
        for (int k = 0; k < KT; ++k) {
            const int kk = t * KT + k;
            unsigned long long hv[4];
#pragma unroll
            for (int rr = 0; rr < 4; ++rr) {
                float h = sh_in[(ty * 4 + rr) * HID + kk];   // warp-broadcast LDS
                hv[rr] = pack2(h, h);
            }
#pragma unroll
            for (int g = 0; g < 4; ++g) {
                ulonglong2 wq = wb[k * 128 + tx + g * 32];   // LDS.128, conflict-free
#pragma unroll
                for (int rr = 0; rr < 4; ++rr) {
                    acc[rr][g][0] = ffma2(hv[rr], wq.x, acc[rr][g][0]);
                    acc[rr][g][1] = ffma2(hv[rr], wq.y, acc[rr][g][1]);
                }
            }
        }
        __syncthreads();
    }

    // epilogue: bias + relu -> sh_out
    float4* out4 = (float4*)sh_out;
#pragma unroll
    for (int rr = 0; rr < 4; ++rr)
#pragma unroll
        for (int g = 0; g < 4; ++g) {
            float a0, a1, a2, a3;
            unpack2(acc[rr][g][0], a0, a1);
            unpack2(acc[rr][g][1], a2, a3);
            a0 = fmaxf(a0 + bq[g].x, 0.f);
            a1 = fmaxf(a1 + bq[g].y, 0.f);
            a2 = fmaxf(a2 + bq[g].z, 0.f);
            a3 = fmaxf(a3 + bq[g].w, 0.f);
            out4[(ty * 4 + rr) * 128 + tx + g * 32] = make_float4(a0, a1, a2, a3);
        }
    __syncthreads();
}

// ---------------- fused kernel: h0 -> L1 -> L2 -> scores ----------------
__global__ void __launch_bounds__(256, 1) fused_kernel(
    const float* __restrict__ W1, const float* __restrict__ b1,
    const float* __restrict__ W2, const float* __restrict__ b2,
    const float* __restrict__ W3, const float* __restrict__ b3,
    float* __restrict__ out)
{
    extern __shared__ float smem[];
    float* bufA = smem;                    // TM*HID = 16384 floats
    float* bufB = smem + TM * HID;         // 16384 floats
    float* wbuf = smem + 2 * TM * HID;     // 2*KT*HID = 16384 floats

    const int tid = threadIdx.x;
    const int blk = blockIdx.x;
    const int i   = blk >> 3;              // 8 blocks per i (256/TM)
    const int j0  = (blk & 7) * TM;

    // h0 = relu(hx[i] + hy[j] (+b0 folded into hx))
    const float4* hx4 = (const float4*)g_hx + i * (HID / 4);
    const float4* hy4 = (const float4*)g_hy;
    float4* bufA4 = (float4*)bufA;
#pragma unroll
    for (int e = 0; e < (TM * HID / 4) / 256; ++e) {   // 16 float4 per thread
        int f = tid + e * 256;
        int r = f >> 7, c4 = f & 127;
        float4 a = hx4[c4];
        float4 b = hy4[(j0 + r) * (HID / 4) + c4];
        bufA4[f] = make_float4(fmaxf(a.x + b.x, 0.f), fmaxf(a.y + b.y, 0.f),
                               fmaxf(a.z + b.z, 0.f), fmaxf(a.w + b.w, 0.f));
    }
    __syncthreads();

    mlp_layer(W1, b1, bufA, bufB, wbuf, tid);   // h1 = relu(h0@W1+b1)
    mlp_layer(W2, b2, bufB, bufA, wbuf, tid);   // h2 = relu(h1@W2+b2)

    // scores = h2 @ W3 + b3 ; each warp handles 4 rows
    const int wid = tid >> 5, lane = tid & 31;
    float w3v[16];
#pragma unroll
    for (int e = 0; e < 16; ++e) w3v[e] = W3[lane + e * 32];

#pragma unroll
    for (int rr = 0; rr < 4; ++rr) {
        const int r = wid * 4 + rr;
        float s = 0.f;
#pragma unroll
        for (int e = 0; e < 16; ++e)
            s = fmaf(bufA[r * HID + lane + e * 32], w3v[e], s);
#pragma unroll
        for (int off = 16; off; off >>= 1)
            s += __shfl_xor_sync(0xffffffffu, s, off);
        if (lane == 0) out[i * B_SZ + j0 + r] = s + b3[0];
    }
}

// ---------------- launch ----------------
extern "C" void kernel_launch(void* const* d_in, const int* in_sizes, int n_in,
                              void* d_out, int out_size)
{
    const float* x  = (const float*)d_in[0];
    const float* y  = (const float*)d_in[1];
    const float* Wx = (const float*)d_in[2];
    const float* Wy = (const float*)d_in[3];
    const float* b0 = (const float*)d_in[4];
    const float* W1 = (const float*)d_in[5];
    const float* b1 = (const float*)d_in[6];
    const float* W2 = (const float*)d_in[7];
    const float* b2 = (const float*)d_in[8];
    const float* W3 = (const float*)d_in[9];
    const float* b3 = (const float*)d_in[10];
    float* out = (float*)d_out;

    const int smem_bytes = 3 * TM * HID * (int)sizeof(float);  // 196608
    cudaFuncSetAttribute(fused_kernel, cudaFuncAttributeMaxDynamicSharedMemorySize, smem_bytes);

    proj_kernel<<<2 * B_SZ, 128>>>(x, y, Wx, Wy, b0);
    fused_kernel<<<(B_SZ * B_SZ) / TM, 256, smem_bytes>>>(W1, b1, W2, b2, W3, b3, out);
}